// round 14
// baseline (speedup 1.0000x reference)
#include <cuda_runtime.h>
#include <cstdint>
#include <cstring>

#define HH 32      // neighbors (== warp size)
#define LLL 4
#define CCC 64
#define CMID 8
#define COUT 64
#define NWARP 4    // warps (== n's) per block
#define NBUF 6     // tile buffers per warp
#define WROW 68    // sWin row stride in floats (swizzled, conflict-free)

// ---------------- cp.async helpers ----------------
__device__ __forceinline__ void cpa16(void* dst, const void* src) {
    unsigned d = (unsigned)__cvta_generic_to_shared(dst);
    asm volatile("cp.async.cg.shared.global [%0], [%1], 16;" :: "r"(d), "l"(src));
}
__device__ __forceinline__ void cpa_commit() { asm volatile("cp.async.commit_group;"); }
template<int K> __device__ __forceinline__ void cpa_wait() {
    asm volatile("cp.async.wait_group %0;" :: "n"(K));
}

__device__ __forceinline__ void ffma2(unsigned long long& acc,
                                      unsigned long long a, unsigned long long b) {
    asm("fma.rn.f32x2 %0, %1, %2, %0;" : "+l"(acc) : "l"(a), "l"(b));
}
__device__ __forceinline__ float2 unpack2(unsigned long long v) {
    float2 f; memcpy(&f, &v, 8); return f;
}
__device__ __forceinline__ ulonglong2 pack4(float4 v) {
    ulonglong2 u; memcpy(&u, &v, 16); return u;
}

// Stage one 1KB tile. Source chunk k (16B) -> smem slot (k>>1) + ((k&1)<<5).
// Consumer: lane i reads slots i and i+32 = floats [8i, 8i+8)  (conflict-free).
__device__ __forceinline__ void stage_issue(float4* b, const float* src, int lane) {
    const int k2 = lane + 32;
    cpa16(b + ((lane >> 1) + ((lane & 1) << 5)), src + lane * 4);
    cpa16(b + ((k2 >> 1) + ((k2 & 1) << 5)),     src + k2 * 4);
    cpa_commit();
}

// Dual 8-lane butterfly reduction, A/B chains interleaved.
__device__ __forceinline__ void reduce8x2(const float* va, const float* vb, int q,
                                          float& outA, float& outB) {
    const unsigned FULL = 0xffffffffu;
    bool s4 = (q & 4) != 0;
    float a0 = (s4 ? va[4] : va[0]) + __shfl_xor_sync(FULL, s4 ? va[0] : va[4], 4);
    float b0 = (s4 ? vb[4] : vb[0]) + __shfl_xor_sync(FULL, s4 ? vb[0] : vb[4], 4);
    float a1 = (s4 ? va[5] : va[1]) + __shfl_xor_sync(FULL, s4 ? va[1] : va[5], 4);
    float b1 = (s4 ? vb[5] : vb[1]) + __shfl_xor_sync(FULL, s4 ? vb[1] : vb[5], 4);
    float a2 = (s4 ? va[6] : va[2]) + __shfl_xor_sync(FULL, s4 ? va[2] : va[6], 4);
    float b2 = (s4 ? vb[6] : vb[2]) + __shfl_xor_sync(FULL, s4 ? vb[2] : vb[6], 4);
    float a3 = (s4 ? va[7] : va[3]) + __shfl_xor_sync(FULL, s4 ? va[3] : va[7], 4);
    float b3 = (s4 ? vb[7] : vb[3]) + __shfl_xor_sync(FULL, s4 ? vb[3] : vb[7], 4);
    bool s2 = (q & 2) != 0;
    float aa0 = (s2 ? a2 : a0) + __shfl_xor_sync(FULL, s2 ? a0 : a2, 2);
    float bb0 = (s2 ? b2 : b0) + __shfl_xor_sync(FULL, s2 ? b0 : b2, 2);
    float aa1 = (s2 ? a3 : a1) + __shfl_xor_sync(FULL, s2 ? a1 : a3, 2);
    float bb1 = (s2 ? b3 : b1) + __shfl_xor_sync(FULL, s2 ? b1 : b3, 2);
    bool s1 = (q & 1) != 0;
    outA = (s1 ? aa1 : aa0) + __shfl_xor_sync(FULL, s1 ? aa0 : aa1, 1);
    outB = (s1 ? bb1 : bb0) + __shfl_xor_sync(FULL, s1 ? bb0 : bb1, 1);
}

// Single-tile variant (prologue msg_s only)
__device__ __forceinline__ float reduce8(const float* v, int q) {
    const unsigned FULL = 0xffffffffu;
    bool s4 = (q & 4) != 0;
    float a0 = (s4 ? v[4] : v[0]) + __shfl_xor_sync(FULL, s4 ? v[0] : v[4], 4);
    float a1 = (s4 ? v[5] : v[1]) + __shfl_xor_sync(FULL, s4 ? v[1] : v[5], 4);
    float a2 = (s4 ? v[6] : v[2]) + __shfl_xor_sync(FULL, s4 ? v[2] : v[6], 4);
    float a3 = (s4 ? v[7] : v[3]) + __shfl_xor_sync(FULL, s4 ? v[3] : v[7], 4);
    bool s2 = (q & 2) != 0;
    float b0c = (s2 ? a2 : a0) + __shfl_xor_sync(FULL, s2 ? a0 : a2, 2);
    float b1c = (s2 ? a3 : a1) + __shfl_xor_sync(FULL, s2 ? a1 : a3, 2);
    bool s1 = (q & 1) != 0;
    return (s1 ? b1c : b0c) + __shfl_xor_sync(FULL, s1 ? b0c : b1c, 1);
}

// Dual-tile 8x8 GEMM, weights streamed from shared (loaded once per m2,
// reused for A and B). qoff = q*8 + (q>>2)*4 (swizzled column offset).
__device__ __forceinline__ void gemm8x2_smem(const float* sw, int qoff,
                                             ulonglong2 a0, ulonglong2 a1,
                                             ulonglong2 b0, ulonglong2 b1,
                                             float* va, float* vb) {
    #pragma unroll
    for (int m2 = 0; m2 < 8; m2++) {
        ulonglong2 w0 = pack4(*reinterpret_cast<const float4*>(sw + m2 * WROW + qoff));
        ulonglong2 w1 = pack4(*reinterpret_cast<const float4*>(sw + m2 * WROW + qoff + 4));
        unsigned long long amA = 0ull, amB = 0ull;
        ffma2(amA, a0.x, w0.x); ffma2(amB, b0.x, w0.x);
        ffma2(amA, a0.y, w0.y); ffma2(amB, b0.y, w0.y);
        ffma2(amA, a1.x, w1.x); ffma2(amB, b1.x, w1.x);
        ffma2(amA, a1.y, w1.y); ffma2(amB, b1.y, w1.y);
        float2 fA = unpack2(amA), fB = unpack2(amB);
        va[m2] = fA.x + fA.y;
        vb[m2] = fB.x + fB.y;
    }
}

__global__ __launch_bounds__(128, 6)
void tp_kernel(const float* __restrict__ s_points,
               const float* __restrict__ nbr_points,
               const float* __restrict__ s_feats,
               const float* __restrict__ nbr_feats,
               const float* __restrict__ W_in,
               const float* __restrict__ W_out,
               const float* __restrict__ w_m0,
               const float* __restrict__ w_m1,
               float* __restrict__ res, int N)
{
    __shared__ float4 sNF[NWARP][NBUF * 64]; // per-warp 6x1KB tile ring (24KB)
    __shared__ float4 sBUT[NWARP][HH * 4];   // per-warp folded Wigner tables (8KB)
    __shared__ float4 sWoutT[CMID * 16];     // W_out^T, even/odd split (2KB)
    __shared__ float  sWin[CMID * WROW];     // W_in half, swizzled (2.2KB) — staged twice

    const int tid  = threadIdx.x;
    const int wid  = tid >> 5;
    const int lane = tid & 31;
    const int l    = lane >> 3;   // 0..3
    const int q    = lane & 7;    // 0..7
    const int qoff = q * 8 + (q >> 2) * 4;   // swizzled weight column offset
    const unsigned FULL = 0xffffffffu;

    // Stage W_out^T (split-swizzled) and W_in S-HALF (cols 64..127) swizzled.
    {
        float* wt = reinterpret_cast<float*>(sWoutT);
        for (int i = tid; i < COUT * CMID; i += 128) {
            int o = i >> 3, mm = i & 7;
            int f = o >> 2;
            int slot = (f >> 1) + ((f & 1) << 3);
            wt[mm * 64 + slot * 4 + (o & 3)] = W_out[i];
        }
        for (int i = tid; i < CMID * CCC; i += 128) {
            int m2 = i >> 6, c = i & 63;
            sWin[m2 * WROW + c + ((c >> 5) << 2)] = W_in[m2 * 128 + 64 + c];
        }
    }
    __syncthreads();

    const int n = blockIdx.x * NWARP + wid;
    const bool active = (n < N);

    float msgs = 0.f;
    float4* buf = sNF[wid];
    const float* nf_src = active ? (nbr_feats + (size_t)n * (HH * LLL * CCC)) : nbr_feats;

    if (active) {
        // ---- start cp.async pipeline: stages 0..3 into buffers 0..3 ----
        stage_issue(buf,       nf_src,       lane);
        stage_issue(buf + 64,  nf_src + 256, lane);
        stage_issue(buf + 128, nf_src + 512, lane);
        stage_issue(buf + 192, nf_src + 768, lane);

        // ---- Wigner D1 + folded tables: lane h handles neighbor h ----
        const float* np = nbr_points + (size_t)n * 96 + lane * 3;
        float vx = __ldg(np + 0) - __ldg(s_points + n * 3 + 0);
        float vy = __ldg(np + 1) - __ldg(s_points + n * 3 + 1);
        float vz = __ldg(np + 2) - __ldg(s_points + n * 3 + 2);
        const float w00 = __ldg(w_m0 + 0), w01 = __ldg(w_m0 + 1);
        const float w10 = __ldg(w_m0 + 2), w11 = __ldg(w_m0 + 3);
        const float wr  = __ldg(w_m1 + 0), wi = __ldg(w_m1 + 1);
        float nrm = sqrtf(vx * vx + vy * vy + vz * vz) + 1e-8f;
        float inv = 1.0f / nrm;
        vx *= inv; vy *= inv; vz *= inv;
        float cb = vz;
        float sb = sqrtf(fmaxf(1.0f - cb * cb, 0.0f));
        float rho2 = vx * vx + vy * vy;
        float ca, sa;
        if (rho2 > 1e-24f) { float ir = rsqrtf(rho2); ca = vx * ir; sa = vy * ir; }
        else               { ca = 1.0f; sa = 0.0f; }
        const float D00 = ca,      D02 = -sa;                 // D01 = 0
        const float D10 = sb * sa, D11 = cb,  D12 = sb * ca;
        const float D20 = cb * sa, D21 = -sb, D22 = cb * ca;
        const float C0x = wr * D00 + wi * D20, C0y = wi * D21, C0z = wr * D02 + wi * D22;
        const float C1x = w11 * D10, C1y = w11 * D11, C1z = w11 * D12;
        const float C2x = wr * D20 - wi * D00, C2y = wr * D21, C2z = wr * D22 - wi * D02;
        float4* tb = &sBUT[wid][lane * 4];
        tb[0] = make_float4(w01 * D10, w01 * D11, w01 * D12, w00);
        tb[1] = make_float4(D00 * C0x + D10 * C1x + D20 * C2x,
                            D00 * C0y + D10 * C1y + D20 * C2y,
                            D00 * C0z + D10 * C1z + D20 * C2z,
                            w10 * D10);
        tb[2] = make_float4(D11 * C1x + D21 * C2x,
                            D11 * C1y + D21 * C2y,
                            D11 * C1z + D21 * C2z,
                            w10 * D11);
        tb[3] = make_float4(D02 * C0x + D12 * C1x + D22 * C2x,
                            D02 * C0y + D12 * C1y + D22 * C2y,
                            D02 * C0z + D12 * C1z + D22 * C2z,
                            w10 * D12);

        // ---- msg_s: s_feats row x sWin (s-half) ----
        const float4* sfp = reinterpret_cast<const float4*>(
            s_feats + (size_t)n * 256 + l * 64 + q * 8);
        ulonglong2 t0 = pack4(__ldg(sfp));
        ulonglong2 t1 = pack4(__ldg(sfp + 1));
        float vals[8];
        #pragma unroll
        for (int m2 = 0; m2 < 8; m2++) {
            ulonglong2 w0 = pack4(*reinterpret_cast<const float4*>(sWin + m2 * WROW + qoff));
            ulonglong2 w1 = pack4(*reinterpret_cast<const float4*>(sWin + m2 * WROW + qoff + 4));
            unsigned long long am = 0ull;
            ffma2(am, t0.x, w0.x);
            ffma2(am, t0.y, w0.y);
            ffma2(am, t1.x, w1.x);
            ffma2(am, t1.y, w1.y);
            float2 f = unpack2(am);
            vals[m2] = f.x + f.y;
        }
        msgs = reduce8(vals, q);
    }

    // Re-stage sWin with the NEIGHBOR half (cols 0..63). All threads sync.
    __syncthreads();
    for (int i = tid; i < CMID * CCC; i += 128) {
        int m2 = i >> 6, c = i & 63;
        sWin[m2 * WROW + c + ((c >> 5) << 2)] = W_in[m2 * 128 + c];
    }
    __syncthreads();
    if (!active) return;

    float acc = 0.f;
    const float4* butw = sBUT[wid];

    // Pair loop: one wait + one syncwarp per 2 tiles; weights from smem.
    int bA = 0;          // buffer of stage hp (partner bA+1; never wraps mid-pair)
    int bP = 4;          // buffer of stage hp+4
    for (int hp = 0; hp < HH; hp += 2) {
        // Entering: pending groups = stages hp..hp+3. Complete hp, hp+1.
        if (hp < HH - 2) { cpa_wait<2>(); } else { cpa_wait<0>(); }
        __syncwarp();

        // Refill stages hp+4, hp+5 into buffers freed at iteration hp-2.
        if (hp + 4 < HH) {
            stage_issue(buf + bP * 64, nf_src + (size_t)(hp + 4) * 256, lane);
            int bP2 = (bP + 1 == NBUF) ? 0 : bP + 1;
            stage_issue(buf + bP2 * 64, nf_src + (size_t)(hp + 5) * 256, lane);
        }

        const float4* bpA = buf + bA * 64;
        ulonglong2 a0 = pack4(bpA[lane]);
        ulonglong2 a1 = pack4(bpA[lane + 32]);
        const float4* bpB = bpA + 64;
        ulonglong2 b0 = pack4(bpB[lane]);
        ulonglong2 b1 = pack4(bpB[lane + 32]);

        float valsA[8], valsB[8];
        gemm8x2_smem(sWin, qoff, a0, a1, b0, b1, valsA, valsB);

        float mA, mB;
        reduce8x2(valsA, valsB, q, mA, mB);
        float msgA = mA + msgs;
        float msgB = mB + msgs;

        float msg0A = __shfl_sync(FULL, msgA, q);
        float msg0B = __shfl_sync(FULL, msgB, q);
        float r1A   = __shfl_sync(FULL, msgA, 8 + q);
        float r1B   = __shfl_sync(FULL, msgB, 8 + q);
        float r2A   = __shfl_sync(FULL, msgA, 16 + q);
        float r2B   = __shfl_sync(FULL, msgB, 16 + q);
        float r3A   = __shfl_sync(FULL, msgA, 24 + q);
        float r3B   = __shfl_sync(FULL, msgB, 24 + q);

        float4 gA = butw[hp * 4 + l];
        float4 gB = butw[hp * 4 + 4 + l];
        acc = fmaf(gA.x, r1A, acc);
        acc = fmaf(gA.y, r2A, acc);
        acc = fmaf(gA.z, r3A, acc);
        acc = fmaf(gA.w, msg0A, acc);
        acc = fmaf(gB.x, r1B, acc);
        acc = fmaf(gB.y, r2B, acc);
        acc = fmaf(gB.z, r3B, acc);
        acc = fmaf(gB.w, msg0B, acc);

        bA += 2; if (bA >= NBUF) bA -= NBUF;
        bP += 2; if (bP >= NBUF) bP -= NBUF;
    }

    // ---- epilogue: res[n,l,o] = sum_mm acc[l][mm] * W_out[o][mm] ----
    float vals8[8];
    #pragma unroll
    for (int mm = 0; mm < 8; mm++) vals8[mm] = __shfl_sync(FULL, acc, l * 8 + mm);

    float4 o0 = make_float4(0.f, 0.f, 0.f, 0.f);
    float4 o1 = make_float4(0.f, 0.f, 0.f, 0.f);
    #pragma unroll
    for (int mm = 0; mm < 8; mm++) {
        float4 wv0 = sWoutT[mm * 16 + q];
        float4 wv1 = sWoutT[mm * 16 + q + 8];
        float v = vals8[mm];
        o0.x = fmaf(v, wv0.x, o0.x); o0.y = fmaf(v, wv0.y, o0.y);
        o0.z = fmaf(v, wv0.z, o0.z); o0.w = fmaf(v, wv0.w, o0.w);
        o1.x = fmaf(v, wv1.x, o1.x); o1.y = fmaf(v, wv1.y, o1.y);
        o1.z = fmaf(v, wv1.z, o1.z); o1.w = fmaf(v, wv1.w, o1.w);
    }
    float4* dst = reinterpret_cast<float4*>(res + (size_t)n * 256 + l * 64 + q * 8);
    dst[0] = o0;
    dst[1] = o1;
}

extern "C" void kernel_launch(void* const* d_in, const int* in_sizes, int n_in,
                              void* d_out, int out_size)
{
    const float* s_points   = (const float*)d_in[0];
    const float* nbr_points = (const float*)d_in[1];
    const float* s_feats    = (const float*)d_in[2];
    const float* nbr_feats  = (const float*)d_in[3];
    // d_in[4] = values (N,H) — unused by the reference computation
    const float* W_in       = (const float*)d_in[5];
    const float* W_out      = (const float*)d_in[6];
    const float* w_m0       = (const float*)d_in[7];
    const float* w_m1       = (const float*)d_in[8];

    const int N = in_sizes[3] / (HH * LLL * CCC);
    const int blocks = (N + NWARP - 1) / NWARP;   // warp per n, 4 warps per block

    tp_kernel<<<blocks, NWARP * 32>>>(s_points, nbr_points, s_feats, nbr_feats,
                                      W_in, W_out, w_m0, w_m1, (float*)d_out, N);
}

// round 17
// speedup vs baseline: 1.2725x; 1.2725x over previous
#include <cuda_runtime.h>
#include <cstdint>
#include <cstring>

#define HH 32      // neighbors (== warp size)
#define LLL 4
#define CCC 64
#define CMID 8
#define COUT 64
#define NWARP 4    // warps (== n's) per block

__device__ __forceinline__ void ffma2(unsigned long long& acc,
                                      unsigned long long a, unsigned long long b) {
    asm("fma.rn.f32x2 %0, %1, %2, %0;" : "+l"(acc) : "l"(a), "l"(b));
}
__device__ __forceinline__ float2 unpack2(unsigned long long v) {
    float2 f; memcpy(&f, &v, 8); return f;
}
__device__ __forceinline__ ulonglong2 pack4(float4 v) {
    ulonglong2 u; memcpy(&u, &v, 16); return u;
}

// Dual 8-lane butterfly reduction, A/B chains interleaved.
__device__ __forceinline__ void reduce8x2(const float* va, const float* vb, int q,
                                          float& outA, float& outB) {
    const unsigned FULL = 0xffffffffu;
    bool s4 = (q & 4) != 0;
    float a0 = (s4 ? va[4] : va[0]) + __shfl_xor_sync(FULL, s4 ? va[0] : va[4], 4);
    float b0 = (s4 ? vb[4] : vb[0]) + __shfl_xor_sync(FULL, s4 ? vb[0] : vb[4], 4);
    float a1 = (s4 ? va[5] : va[1]) + __shfl_xor_sync(FULL, s4 ? va[1] : va[5], 4);
    float b1 = (s4 ? vb[5] : vb[1]) + __shfl_xor_sync(FULL, s4 ? vb[1] : vb[5], 4);
    float a2 = (s4 ? va[6] : va[2]) + __shfl_xor_sync(FULL, s4 ? va[2] : va[6], 4);
    float b2 = (s4 ? vb[6] : vb[2]) + __shfl_xor_sync(FULL, s4 ? vb[2] : vb[6], 4);
    float a3 = (s4 ? va[7] : va[3]) + __shfl_xor_sync(FULL, s4 ? va[3] : va[7], 4);
    float b3 = (s4 ? vb[7] : vb[3]) + __shfl_xor_sync(FULL, s4 ? vb[3] : vb[7], 4);
    bool s2 = (q & 2) != 0;
    float aa0 = (s2 ? a2 : a0) + __shfl_xor_sync(FULL, s2 ? a0 : a2, 2);
    float bb0 = (s2 ? b2 : b0) + __shfl_xor_sync(FULL, s2 ? b0 : b2, 2);
    float aa1 = (s2 ? a3 : a1) + __shfl_xor_sync(FULL, s2 ? a1 : a3, 2);
    float bb1 = (s2 ? b3 : b1) + __shfl_xor_sync(FULL, s2 ? b1 : b3, 2);
    bool s1 = (q & 1) != 0;
    outA = (s1 ? aa1 : aa0) + __shfl_xor_sync(FULL, s1 ? aa0 : aa1, 1);
    outB = (s1 ? bb1 : bb0) + __shfl_xor_sync(FULL, s1 ? bb0 : bb1, 1);
}

// Single-tile variant (prologue msg_s only)
__device__ __forceinline__ float reduce8(const float* v, int q) {
    const unsigned FULL = 0xffffffffu;
    bool s4 = (q & 4) != 0;
    float a0 = (s4 ? v[4] : v[0]) + __shfl_xor_sync(FULL, s4 ? v[0] : v[4], 4);
    float a1 = (s4 ? v[5] : v[1]) + __shfl_xor_sync(FULL, s4 ? v[1] : v[5], 4);
    float a2 = (s4 ? v[6] : v[2]) + __shfl_xor_sync(FULL, s4 ? v[2] : v[6], 4);
    float a3 = (s4 ? v[7] : v[3]) + __shfl_xor_sync(FULL, s4 ? v[3] : v[7], 4);
    bool s2 = (q & 2) != 0;
    float b0c = (s2 ? a2 : a0) + __shfl_xor_sync(FULL, s2 ? a0 : a2, 2);
    float b1c = (s2 ? a3 : a1) + __shfl_xor_sync(FULL, s2 ? a1 : a3, 2);
    bool s1 = (q & 1) != 0;
    return (s1 ? b1c : b0c) + __shfl_xor_sync(FULL, s1 ? b0c : b1c, 1);
}

// Dual-tile 8x8 GEMM with register-resident weights, A/B interleaved.
__device__ __forceinline__ void gemm8x2(const unsigned long long* wb,
                                        ulonglong2 a0, ulonglong2 a1,
                                        ulonglong2 b0, ulonglong2 b1,
                                        float* va, float* vb) {
    #pragma unroll
    for (int m2 = 0; m2 < 8; m2++) {
        unsigned long long amA = 0ull, amB = 0ull;
        ffma2(amA, a0.x, wb[m2 * 4 + 0]); ffma2(amB, b0.x, wb[m2 * 4 + 0]);
        ffma2(amA, a0.y, wb[m2 * 4 + 1]); ffma2(amB, b0.y, wb[m2 * 4 + 1]);
        ffma2(amA, a1.x, wb[m2 * 4 + 2]); ffma2(amB, b1.x, wb[m2 * 4 + 2]);
        ffma2(amA, a1.y, wb[m2 * 4 + 3]); ffma2(amB, b1.y, wb[m2 * 4 + 3]);
        float2 fA = unpack2(amA), fB = unpack2(amB);
        va[m2] = fA.x + fA.y;
        vb[m2] = fB.x + fB.y;
    }
}

__global__ __launch_bounds__(128, 4)
void tp_kernel(const float* __restrict__ s_points,
               const float* __restrict__ nbr_points,
               const float* __restrict__ s_feats,
               const float* __restrict__ nbr_feats,
               const float* __restrict__ W_in,
               const float* __restrict__ W_out,
               const float* __restrict__ w_m0,
               const float* __restrict__ w_m1,
               float* __restrict__ res, int N)
{
    __shared__ float4 sBUT[NWARP][HH * 4];   // per-warp folded Wigner tables (8KB)
    __shared__ float4 sWoutT[CMID * 16];     // W_out^T, even/odd split (2KB)

    const int tid  = threadIdx.x;
    const int wid  = tid >> 5;
    const int lane = tid & 31;
    const int l    = lane >> 3;   // 0..3
    const int q    = lane & 7;    // 0..7
    const unsigned FULL = 0xffffffffu;

    // Stage W_out transposed + split-swizzled.
    {
        float* wt = reinterpret_cast<float*>(sWoutT);
        for (int i = tid; i < COUT * CMID; i += 128) {
            int o = i >> 3, mm = i & 7;
            int f = o >> 2;
            int slot = (f >> 1) + ((f & 1) << 3);
            wt[mm * 64 + slot * 4 + (o & 3)] = W_out[i];
        }
    }
    __syncthreads();

    const int n = blockIdx.x * NWARP + wid;
    if (n >= N) return;   // whole warp; no block syncs below

    const float w00 = __ldg(w_m0 + 0), w01 = __ldg(w_m0 + 1);
    const float w10 = __ldg(w_m0 + 2), w11 = __ldg(w_m0 + 3);
    const float wr  = __ldg(w_m1 + 0), wi = __ldg(w_m1 + 1);

    // ---- Wigner D1 + folded tables: lane h handles neighbor h (H==32) ----
    // out[0]  = w00*msg0 + w01*(D_row1 . v)
    // out[1+i]= (D^T A D)[i] . v + w10*D[1][i]*msg0
    {
        const float* np = nbr_points + (size_t)n * 96 + lane * 3;
        float vx = __ldg(np + 0) - __ldg(s_points + n * 3 + 0);
        float vy = __ldg(np + 1) - __ldg(s_points + n * 3 + 1);
        float vz = __ldg(np + 2) - __ldg(s_points + n * 3 + 2);
        float nrm = sqrtf(vx * vx + vy * vy + vz * vz) + 1e-8f;
        float inv = 1.0f / nrm;
        vx *= inv; vy *= inv; vz *= inv;
        float cb = vz;
        float sb = sqrtf(fmaxf(1.0f - cb * cb, 0.0f));
        float rho2 = vx * vx + vy * vy;
        float ca, sa;
        if (rho2 > 1e-24f) { float ir = rsqrtf(rho2); ca = vx * ir; sa = vy * ir; }
        else               { ca = 1.0f; sa = 0.0f; }
        const float D00 = ca,      D02 = -sa;                 // D01 = 0
        const float D10 = sb * sa, D11 = cb,  D12 = sb * ca;
        const float D20 = cb * sa, D21 = -sb, D22 = cb * ca;
        // C = A*D, A = [[wr,0,wi],[0,w11,0],[-wi,0,wr]]
        const float C0x = wr * D00 + wi * D20, C0y = wi * D21, C0z = wr * D02 + wi * D22;
        const float C1x = w11 * D10, C1y = w11 * D11, C1z = w11 * D12;
        const float C2x = wr * D20 - wi * D00, C2y = wr * D21, C2z = wr * D22 - wi * D02;
        float4* tb = &sBUT[wid][lane * 4];
        tb[0] = make_float4(w01 * D10, w01 * D11, w01 * D12, w00);
        tb[1] = make_float4(D00 * C0x + D10 * C1x + D20 * C2x,
                            D00 * C0y + D10 * C1y + D20 * C2y,
                            D00 * C0z + D10 * C1z + D20 * C2z,
                            w10 * D10);
        tb[2] = make_float4(D11 * C1x + D21 * C2x,
                            D11 * C1y + D21 * C2y,
                            D11 * C1z + D21 * C2z,
                            w10 * D11);
        tb[3] = make_float4(D02 * C0x + D12 * C1x + D22 * C2x,
                            D02 * C0y + D12 * C1y + D22 * C2y,
                            D02 * C0z + D12 * C1z + D22 * C2z,
                            w10 * D12);
    }

    // 8x8 weight block per lane (cols q*8..q*8+8 for all 8 m rows), packed.
    unsigned long long wb[32];

    // ---- msg_s once (s-feature half of W_in) ----
    float msgs;
    {
        const float* base = W_in + 64 + q * 8;
        #pragma unroll
        for (int m2 = 0; m2 < 8; m2++) {
            const float4* p = reinterpret_cast<const float4*>(base + m2 * 128);
            ulonglong2 ua = pack4(__ldg(p));
            ulonglong2 ub = pack4(__ldg(p + 1));
            wb[m2 * 4 + 0] = ua.x; wb[m2 * 4 + 1] = ua.y;
            wb[m2 * 4 + 2] = ub.x; wb[m2 * 4 + 3] = ub.y;
        }
        const float4* sfp = reinterpret_cast<const float4*>(
            s_feats + (size_t)n * 256 + l * 64 + q * 8);
        ulonglong2 t0 = pack4(__ldg(sfp));
        ulonglong2 t1 = pack4(__ldg(sfp + 1));
        float vals[8];
        #pragma unroll
        for (int m2 = 0; m2 < 8; m2++) {
            unsigned long long am = 0ull;
            ffma2(am, t0.x, wb[m2 * 4 + 0]);
            ffma2(am, t0.y, wb[m2 * 4 + 1]);
            ffma2(am, t1.x, wb[m2 * 4 + 2]);
            ffma2(am, t1.y, wb[m2 * 4 + 3]);
            float2 f = unpack2(am);
            vals[m2] = f.x + f.y;
        }
        msgs = reduce8(vals, q);
    }
    // Neighbor-half weights, loop-invariant in regs
    {
        const float* base = W_in + q * 8;
        #pragma unroll
        for (int m2 = 0; m2 < 8; m2++) {
            const float4* p = reinterpret_cast<const float4*>(base + m2 * 128);
            ulonglong2 ua = pack4(__ldg(p));
            ulonglong2 ub = pack4(__ldg(p + 1));
            wb[m2 * 4 + 0] = ua.x; wb[m2 * 4 + 1] = ua.y;
            wb[m2 * 4 + 2] = ub.x; wb[m2 * 4 + 3] = ub.y;
        }
    }
    __syncwarp();   // sBUT writes visible to all lanes before the loop

    float acc = 0.f;
    const float4* butw = sBUT[wid];

    // Lane's fixed slice: floats [8*lane, 8*lane+8) of each 1KB tile.
    // Tile t = (float4*)nf_src + t*64; lane reads slots lane*2, lane*2+1.
    const float4* tsrc = reinterpret_cast<const float4*>(
        nbr_feats + (size_t)n * (HH * LLL * CCC)) + lane * 2;

    // Software-pipelined pair loop, all data in registers — NO barriers,
    // NO shared-memory staging. Next pair's 4 LDG.128 issue before this
    // pair's compute consumes its registers (one-pair prefetch distance).
    ulonglong2 a0 = pack4(__ldg(tsrc + 0 * 64));
    ulonglong2 a1 = pack4(__ldg(tsrc + 0 * 64 + 1));
    ulonglong2 b0 = pack4(__ldg(tsrc + 1 * 64));
    ulonglong2 b1 = pack4(__ldg(tsrc + 1 * 64 + 1));

    #pragma unroll 2
    for (int hp = 0; hp < HH; hp += 2) {
        // Prefetch pair hp+2 (clamped index keeps the loads in-bounds on the
        // final iteration; values unused there).
        const int t2 = (hp + 2 < HH) ? (hp + 2) : 0;
        ulonglong2 na0 = pack4(__ldg(tsrc + t2 * 64));
        ulonglong2 na1 = pack4(__ldg(tsrc + t2 * 64 + 1));
        ulonglong2 nb0 = pack4(__ldg(tsrc + (t2 + 1) * 64));
        ulonglong2 nb1 = pack4(__ldg(tsrc + (t2 + 1) * 64 + 1));

        float valsA[8], valsB[8];
        gemm8x2(wb, a0, a1, b0, b1, valsA, valsB);

        float mA, mB;
        reduce8x2(valsA, valsB, q, mA, mB);
        float msgA = mA + msgs;
        float msgB = mB + msgs;

        float msg0A = __shfl_sync(FULL, msgA, q);
        float msg0B = __shfl_sync(FULL, msgB, q);
        float r1A   = __shfl_sync(FULL, msgA, 8 + q);
        float r1B   = __shfl_sync(FULL, msgB, 8 + q);
        float r2A   = __shfl_sync(FULL, msgA, 16 + q);
        float r2B   = __shfl_sync(FULL, msgB, 16 + q);
        float r3A   = __shfl_sync(FULL, msgA, 24 + q);
        float r3B   = __shfl_sync(FULL, msgB, 24 + q);

        float4 gA = butw[hp * 4 + l];
        float4 gB = butw[hp * 4 + 4 + l];
        acc = fmaf(gA.x, r1A, acc);
        acc = fmaf(gA.y, r2A, acc);
        acc = fmaf(gA.z, r3A, acc);
        acc = fmaf(gA.w, msg0A, acc);
        acc = fmaf(gB.x, r1B, acc);
        acc = fmaf(gB.y, r2B, acc);
        acc = fmaf(gB.z, r3B, acc);
        acc = fmaf(gB.w, msg0B, acc);

        a0 = na0; a1 = na1; b0 = nb0; b1 = nb1;
    }

    // ---- epilogue: res[n,l,o] = sum_mm acc[l][mm] * W_out[o][mm] ----
    float vals8[8];
    #pragma unroll
    for (int mm = 0; mm < 8; mm++) vals8[mm] = __shfl_sync(FULL, acc, l * 8 + mm);

    float4 o0 = make_float4(0.f, 0.f, 0.f, 0.f);
    float4 o1 = make_float4(0.f, 0.f, 0.f, 0.f);
    #pragma unroll
    for (int mm = 0; mm < 8; mm++) {
        float4 wv0 = sWoutT[mm * 16 + q];
        float4 wv1 = sWoutT[mm * 16 + q + 8];
        float v = vals8[mm];
        o0.x = fmaf(v, wv0.x, o0.x); o0.y = fmaf(v, wv0.y, o0.y);
        o0.z = fmaf(v, wv0.z, o0.z); o0.w = fmaf(v, wv0.w, o0.w);
        o1.x = fmaf(v, wv1.x, o1.x); o1.y = fmaf(v, wv1.y, o1.y);
        o1.z = fmaf(v, wv1.z, o1.z); o1.w = fmaf(v, wv1.w, o1.w);
    }
    float4* dst = reinterpret_cast<float4*>(res + (size_t)n * 256 + l * 64 + q * 8);
    dst[0] = o0;
    dst[1] = o1;
}

extern "C" void kernel_launch(void* const* d_in, const int* in_sizes, int n_in,
                              void* d_out, int out_size)
{
    const float* s_points   = (const float*)d_in[0];
    const float* nbr_points = (const float*)d_in[1];
    const float* s_feats    = (const float*)d_in[2];
    const float* nbr_feats  = (const float*)d_in[3];
    // d_in[4] = values (N,H) — unused by the reference computation
    const float* W_in       = (const float*)d_in[5];
    const float* W_out      = (const float*)d_in[6];
    const float* w_m0       = (const float*)d_in[7];
    const float* w_m1       = (const float*)d_in[8];

    const int N = in_sizes[3] / (HH * LLL * CCC);
    const int blocks = (N + NWARP - 1) / NWARP;   // warp per n, 4 warps per block

    tp_kernel<<<blocks, NWARP * 32>>>(s_points, nbr_points, s_feats, nbr_feats,
                                      W_in, W_out, w_m0, w_m1, (float*)d_out, N);
}